// round 6
// baseline (speedup 1.0000x reference)
#include <cuda_runtime.h>
#include <cstdint>

// NearestEmbed, packed-f32x2 SIMT GEMM + fused argmin.
// R6: 512 threads/CTA (4 warps/SMSP) for latency hiding; thread tile 4px x 16codes.
// Arithmetic bit-identical to R1/R5 (rel_err 0.0):
//   xe[px,k]: fp32 fma chain over d ascending (f32x2 packed = same per-lane rounding)
//   x2/e2:    sequential fadd(rn(v*v)) over d ascending
//   d2 = fadd(fadd(x2, fmul(-2,xe)), e2); first-index tie-break via packed atomicMin.

#define DCH 128
#define KCODES 1024
#define HW 4096
#define BATCH 32
#define RES_ELEMS ((size_t)BATCH * DCH * HW)

#define MTILE 128          // pixels per CTA
#define NSTAGE 256         // codes per stage
#define NPHASES 8          // 4 stages x 2 d-chunks of 64
#define NTHREADS 512
#define WROW 1136          // bytes per d-row: 71 slots x 16B (64 granules + pads)
#define WSBUF (64 * WROW)  // 72704 bytes per chunk buffer

#define OFF_XS 0                       // [128d][128px] f32 = 65536
#define OFF_WS 65536                   // 2 x WSBUF = 145408
#define OFF_X2 210944                  // 128 f32
#define OFF_E2 211456                  // 256 f32
#define OFF_BEST 212480                // 128 u64
#define SMEM_TOTAL 213504

__device__ __forceinline__ uint32_t smem_u32(const void* p) {
    uint32_t a;
    asm("{ .reg .u64 t; cvta.to.shared.u64 t, %1; cvt.u32.u64 %0, t; }" : "=r"(a) : "l"(p));
    return a;
}
__device__ __forceinline__ void cp16(uint32_t dst, const void* src) {
    asm volatile("cp.async.cg.shared.global [%0], [%1], 16;" :: "r"(dst), "l"(src) : "memory");
}
#define CP_COMMIT() asm volatile("cp.async.commit_group;" ::: "memory")
#define CP_WAIT(N)  asm volatile("cp.async.wait_group %0;" :: "n"(N) : "memory")

#define FMA2(A, X, W) \
    asm("fma.rn.f32x2 %0, %1, %2, %3;" : "=l"(A) : "l"(X), "l"(W), "l"(A))
#define DUP2(D, F) \
    asm("mov.b64 %0, {%1, %1};" : "=l"(D) : "r"(__float_as_uint(F)))
#define UNPK(LO, HI, P) \
    asm("mov.b64 {%0, %1}, %2;" : "=r"(LO), "=r"(HI) : "l"(P))

// injective granule swizzle: granule q (16B) of a d-row -> byte (q + (q>>3)) * 16
__device__ __forceinline__ uint32_t granule_off(uint32_t q) {
    return (q + (q >> 3)) << 4;
}
// byte offset of 16-code group tx (granules 4tx..4tx+3, always contiguous 64B)
__device__ __forceinline__ uint32_t group_off(uint32_t tx) {
    return tx * 64u + (tx >> 1) * 16u;
}

__global__ __launch_bounds__(NTHREADS, 1)
void nearest_embed_f32x2_kernel(const float* __restrict__ x,
                                const float* __restrict__ w,
                                float* __restrict__ out,
                                int write_amin) {
    extern __shared__ char smem[];
    const uint32_t su = smem_u32(smem);
    const int tid = threadIdx.x;
    const int blk = blockIdx.x;
    const int b = blk >> 5;
    const int hw0 = (blk & 31) * MTILE;

    float* x2s = (float*)(smem + OFF_X2);
    float* e2s = (float*)(smem + OFF_E2);
    unsigned long long* best = (unsigned long long*)(smem + OFF_BEST);

    const int tx = tid & 15;           // code group (16 codes)
    const int ty = tid >> 4;           // pixel group (4 px), 0..31
    const int px0 = ty * 4;

    if (tid < MTILE) best[tid] = 0xFFFFFFFFFFFFFFFFull;

    // ---- async load x tile [128d][128px] ----
    const float* xbase = x + ((size_t)b * DCH) * HW + hw0;
    for (int t = tid; t < DCH * 32; t += NTHREADS) {   // 32 float4 per d-row
        int d = t >> 5, q = t & 31;
        cp16(su + OFF_XS + (uint32_t)(d * 512 + q * 16),
             xbase + (size_t)d * HW + q * 4);
    }
    CP_COMMIT();

    // ---- async load ws chunks 0 and 1 (stage 0) ----
    for (int cc = 0; cc < 2; ++cc) {
        const float* src = w + (size_t)(cc * 64) * KCODES;   // stage 0, codes 0..255
        uint32_t dbuf = su + OFF_WS + cc * WSBUF;
        for (int t = tid; t < 4096; t += NTHREADS) {         // 64 rows x 64 granules
            int dr = t >> 6, q = t & 63;
            cp16(dbuf + (uint32_t)(dr * WROW) + granule_off((uint32_t)q),
                 src + (size_t)dr * KCODES + q * 4);
        }
        CP_COMMIT();
    }

    // ---- x2 (needs xs only) ----
    CP_WAIT(2);
    __syncthreads();
    if (tid < MTILE) {
        const float* col = (const float*)(smem + OFF_XS) + tid;
        float a = 0.0f;
        for (int d = 0; d < DCH; ++d) {
            float v = col[d * MTILE];
            a = __fadd_rn(a, __fmul_rn(v, v));
        }
        x2s[tid] = a;
    }
    __syncthreads();

    float x2v[4];
#pragma unroll
    for (int i = 0; i < 4; ++i) x2v[i] = x2s[px0 + i];

    unsigned long long acc[4][8];
    float bd[4];
    int bk[4];
#pragma unroll
    for (int i = 0; i < 4; ++i) { bd[i] = __int_as_float(0x7F800000); bk[i] = 0; }

    const uint32_t wsel = group_off((uint32_t)tx);   // this thread's code-group offset
    const uint32_t e2off = granule_off((uint32_t)((tid & 255) >> 2)) + (tid & 3) * 4;

    for (int m = 0; m < NPHASES; ++m) {
        // ---- wait for chunk m ----
        if (m < NPHASES - 1) { CP_WAIT(1); } else { CP_WAIT(0); }
        __syncthreads();

        const char* buf = smem + OFF_WS + (m & 1) * WSBUF;

        // ---- e2 partial for this chunk (threads 0..255 -> stage-local code) ----
        if (tid < NSTAGE) {
            float a = (m & 1) ? e2s[tid] : 0.0f;
            const char* p = buf + e2off;
#pragma unroll 4
            for (int dr = 0; dr < 64; ++dr) {
                float v = *(const float*)(p + dr * WROW);
                a = __fadd_rn(a, __fmul_rn(v, v));
            }
            e2s[tid] = a;
        }

        // ---- main FMA: 64 d-steps, 4px x 16codes per thread ----
        if ((m & 1) == 0) {
#pragma unroll
            for (int i = 0; i < 4; ++i)
#pragma unroll
                for (int jp = 0; jp < 8; ++jp) acc[i][jp] = 0ull;
        }
        {
            const char* wb = buf + wsel;
            const char* xb = smem + OFF_XS + (m & 1) * (64 * 512) + px0 * 4;
#pragma unroll 2
            for (int dr = 0; dr < 64; ++dr) {
                const ulonglong2 w0 = *(const ulonglong2*)(wb + dr * WROW);
                const ulonglong2 w1 = *(const ulonglong2*)(wb + dr * WROW + 16);
                const ulonglong2 w2 = *(const ulonglong2*)(wb + dr * WROW + 32);
                const ulonglong2 w3 = *(const ulonglong2*)(wb + dr * WROW + 48);
                const float4 xa = *(const float4*)(xb + dr * 512);
                const float xf[4] = {xa.x, xa.y, xa.z, xa.w};
                const unsigned long long wd[8] = {w0.x, w0.y, w1.x, w1.y,
                                                  w2.x, w2.y, w3.x, w3.y};
                unsigned long long xd[4];
#pragma unroll
                for (int i = 0; i < 4; ++i) DUP2(xd[i], xf[i]);
#pragma unroll
                for (int i = 0; i < 4; ++i)
#pragma unroll
                    for (int jp = 0; jp < 8; ++jp)
                        FMA2(acc[i][jp], xd[i], wd[jp]);
            }
        }

        __syncthreads();   // all reads of buf done; e2s visible

        // ---- prefetch chunk m+2 into buf(m&1) ----
        if (m < NPHASES - 2) {
            const int mp = m + 2;
            const int s2 = mp >> 1, cc2 = mp & 1;
            const float* src = w + (size_t)(cc2 * 64) * KCODES + s2 * NSTAGE;
            uint32_t dbuf = su + OFF_WS + (m & 1) * WSBUF;
            for (int t = tid; t < 4096; t += NTHREADS) {
                int dr = t >> 6, q = t & 63;
                cp16(dbuf + (uint32_t)(dr * WROW) + granule_off((uint32_t)q),
                     src + (size_t)dr * KCODES + q * 4);
            }
            CP_COMMIT();
        }

        // ---- stage epilogue after second chunk ----
        if (m & 1) {
            const int kbase = (m >> 1) * NSTAGE + tx * 16;
#pragma unroll
            for (int i = 0; i < 4; ++i) {
                const float xv = x2v[i];
#pragma unroll
                for (int jp = 0; jp < 8; ++jp) {
                    uint32_t lo, hi;
                    UNPK(lo, hi, acc[i][jp]);
                    float xel = __uint_as_float(lo);
                    float t0 = __fadd_rn(xv, __fmul_rn(-2.0f, xel));
                    float d2l = __fadd_rn(t0, e2s[tx * 16 + 2 * jp]);
                    if (d2l < bd[i]) { bd[i] = d2l; bk[i] = kbase + 2 * jp; }
                    float xeh = __uint_as_float(hi);
                    float t1 = __fadd_rn(xv, __fmul_rn(-2.0f, xeh));
                    float d2h = __fadd_rn(t1, e2s[tx * 16 + 2 * jp + 1]);
                    if (d2h < bd[i]) { bd[i] = d2h; bk[i] = kbase + 2 * jp + 1; }
                }
            }
        }
    }

    // ---- merge across the 16 threads sharing each pixel ----
#pragma unroll
    for (int i = 0; i < 4; ++i) {
        unsigned long long pack =
            ((unsigned long long)__float_as_uint(bd[i]) << 32) | (unsigned)bk[i];
        atomicMin(&best[px0 + i], pack);
    }
    __syncthreads();

    // ---- outputs: gather codebook rows + argmin ----
    const size_t obase = ((size_t)b * DCH) * HW + hw0;
    for (int t = tid; t < DCH * MTILE; t += NTHREADS) {
        int d = t >> 7;
        int px = t & 127;
        unsigned k = (unsigned)(best[px] & 0xFFFFFFFFu);
        out[obase + (size_t)d * HW + px] = w[(size_t)d * KCODES + k];
    }
    if (write_amin && tid < MTILE) {
        unsigned k = (unsigned)(best[tid] & 0xFFFFFFFFu);
        out[RES_ELEMS + (size_t)b * HW + hw0 + tid] = (float)k;
    }
}

extern "C" void kernel_launch(void* const* d_in, const int* in_sizes, int n_in,
                              void* d_out, int out_size) {
    const float* x = (const float*)d_in[0];
    const float* w = (const float*)d_in[1];
    float* out = (float*)d_out;
    const int write_amin = ((size_t)out_size > RES_ELEMS) ? 1 : 0;

    cudaFuncSetAttribute(nearest_embed_f32x2_kernel,
                         cudaFuncAttributeMaxDynamicSharedMemorySize, SMEM_TOTAL);
    nearest_embed_f32x2_kernel<<<(BATCH * HW) / MTILE, NTHREADS, SMEM_TOTAL>>>(
        x, w, out, write_amin);
}

// round 7
// speedup vs baseline: 1.4509x; 1.4509x over previous
#include <cuda_runtime.h>
#include <cuda_bf16.h>
#include <cstdint>

// NearestEmbed via mma.sync (HMMA) bf16 3-split GEMM + fused argmin.
//   xe = x.w via 6 bf16 mma combos (x0..2, w0..2, sa+sb<=2), fp32 accum.
//   x2/e2: sequential fadd(rn(v*v)) ascending d (bit-identical to reference path)
//   d2 = fadd(fadd(x2, fmul(-2,xe)), e2); first-index tie-break, packed atomicMin.

#define DCH 128
#define KCODES 1024
#define HW 4096
#define BATCH 32
#define RES_ELEMS ((size_t)BATCH * DCH * HW)

#define NTHREADS 256
#define MTILE 128            // pixels per CTA
#define NSTAGE 64            // codes per stage
#define NSTAGES 16

#define A_SPLIT 32768        // one bf16 split of x tile: 8 chunks x 128px x 32B
#define W_SPLIT 16384        // one bf16 split of w stage: 8 chunks x 64c x 32B
#define W_STAGE (3 * W_SPLIT)

#define OFF_A    0           // 3 x A_SPLIT = 98304
#define OFF_W    98304       // 2 x W_STAGE = 98304
#define OFF_XF   98304       // overlay: x f32 tile [128d][128px] = 65536 (pre-loop)
#define OFF_E2   196608      // 1024 f32
#define OFF_X2   200704      // 128 f32
#define OFF_BEST 201216      // 128 u64
#define SMEM_TOTAL 202240

__device__ __align__(16) unsigned char g_wsplit[NSTAGES * W_STAGE];
__device__ float g_e2[KCODES];

// ---------------- helpers ----------------
__device__ __forceinline__ uint32_t smem_u32(const void* p) {
    uint32_t a;
    asm("{ .reg .u64 t; cvta.to.shared.u64 t, %1; cvt.u32.u64 %0, t; }" : "=r"(a) : "l"(p));
    return a;
}
__device__ __forceinline__ void cp16(uint32_t dst, const void* src) {
    asm volatile("cp.async.cg.shared.global [%0], [%1], 16;" :: "r"(dst), "l"(src) : "memory");
}
#define CP_COMMIT() asm volatile("cp.async.commit_group;" ::: "memory")
#define CP_WAIT(N)  asm volatile("cp.async.wait_group %0;" :: "n"(N) : "memory")

#define LDSM_X4(R0, R1, R2, R3, ADDR) \
    asm volatile("ldmatrix.sync.aligned.m8n8.x4.shared.b16 {%0,%1,%2,%3}, [%4];" \
        : "=r"(R0), "=r"(R1), "=r"(R2), "=r"(R3) : "r"(ADDR))

#define MMA16816(D, A, B0, B1) \
    asm volatile("mma.sync.aligned.m16n8k16.row.col.f32.bf16.bf16.f32 " \
        "{%0,%1,%2,%3}, {%4,%5,%6,%7}, {%8,%9}, {%0,%1,%2,%3};" \
        : "+f"((D)[0]), "+f"((D)[1]), "+f"((D)[2]), "+f"((D)[3]) \
        : "r"((A)[0]), "r"((A)[1]), "r"((A)[2]), "r"((A)[3]), "r"(B0), "r"(B1))

// XOR-swizzled granule offset: row p (4 px/codes per 128B row), k-half h.
// 16B granule column permuted within its 128B row -> ldmatrix conflict-free.
__device__ __host__ __forceinline__ uint32_t swz16(uint32_t p, uint32_t h) {
    uint32_t r = p >> 2;
    uint32_t col = (((p & 3u) * 2u + h) ^ (r & 7u));
    return r * 128u + col * 16u;
}

__device__ __forceinline__ void split3(float v, unsigned short& s0, unsigned short& s1,
                                       unsigned short& s2) {
    __nv_bfloat16 h0 = __float2bfloat16_rn(v);
    float f0 = __bfloat162float(h0);
    float r1 = v - f0;
    __nv_bfloat16 h1 = __float2bfloat16_rn(r1);
    float f1 = __bfloat162float(h1);
    float r2 = r1 - f1;
    __nv_bfloat16 h2 = __float2bfloat16_rn(r2);
    s0 = __bfloat16_as_ushort(h0);
    s1 = __bfloat16_as_ushort(h1);
    s2 = __bfloat16_as_ushort(h2);
}
__device__ __forceinline__ uint4 pack8(const unsigned short* s) {
    uint4 v;
    v.x = (uint32_t)s[0] | ((uint32_t)s[1] << 16);
    v.y = (uint32_t)s[2] | ((uint32_t)s[3] << 16);
    v.z = (uint32_t)s[4] | ((uint32_t)s[5] << 16);
    v.w = (uint32_t)s[6] | ((uint32_t)s[7] << 16);
    return v;
}

// ---------------- prep: split w into cp.async-ready swizzled stages + e2 ----------------
__global__ void convert_w_kernel(const float* __restrict__ w) {
    const int nt = blockIdx.x;        // stage (64 codes)
    const int c = threadIdx.x;        // local code 0..63
    const int k = nt * NSTAGE + c;
    float e2 = 0.0f;
    for (int g = 0; g < 16; ++g) {    // granule g covers d = 8g..8g+7 (ascending)
        unsigned short s0[8], s1[8], s2[8];
#pragma unroll
        for (int j = 0; j < 8; ++j) {
            float v = w[(size_t)(g * 8 + j) * KCODES + k];
            e2 = __fadd_rn(e2, __fmul_rn(v, v));
            split3(v, s0[j], s1[j], s2[j]);
        }
        const int ch = g >> 1, h = g & 1;
        unsigned char* base = g_wsplit + (size_t)nt * W_STAGE + (size_t)ch * 2048
                            + swz16((uint32_t)c, (uint32_t)h);
        *(uint4*)(base + 0 * W_SPLIT) = pack8(s0);
        *(uint4*)(base + 1 * W_SPLIT) = pack8(s1);
        *(uint4*)(base + 2 * W_SPLIT) = pack8(s2);
    }
    g_e2[k] = e2;
}

// ---------------- main ----------------
__global__ __launch_bounds__(NTHREADS, 1)
void nearest_embed_hmma_kernel(const float* __restrict__ x,
                               const float* __restrict__ w,
                               float* __restrict__ out,
                               int write_amin) {
    extern __shared__ char smem[];
    const uint32_t su = smem_u32(smem);
    const int tid = threadIdx.x;
    const int blk = blockIdx.x;
    const int b = blk >> 5;
    const int hw0 = (blk & 31) * MTILE;

    float* e2s = (float*)(smem + OFF_E2);
    float* x2s = (float*)(smem + OFF_X2);
    unsigned long long* best = (unsigned long long*)(smem + OFF_BEST);

    if (tid < MTILE) best[tid] = 0xFFFFFFFFFFFFFFFFull;
    for (int i = tid; i < KCODES; i += NTHREADS) e2s[i] = g_e2[i];

    // ---- stage x f32 tile [128d][128px] into OFF_XF ----
    const float* xbase = x + ((size_t)b * DCH) * HW + hw0;
    for (int t = tid; t < DCH * 32; t += NTHREADS) {
        int d = t >> 5, q = t & 31;
        cp16(su + OFF_XF + (uint32_t)(d * 512 + q * 16),
             xbase + (size_t)d * HW + q * 4);
    }
    CP_COMMIT();
    CP_WAIT(0);
    __syncthreads();

    // ---- x2 (exact sequential ascending d) ----
    const float* xf = (const float*)(smem + OFF_XF);
    if (tid < MTILE) {
        float a = 0.0f;
        for (int d = 0; d < DCH; ++d) {
            float v = xf[d * MTILE + tid];
            a = __fadd_rn(a, __fmul_rn(v, v));
        }
        x2s[tid] = a;
    }

    // ---- convert x tile -> 3 bf16 splits (swizzled A layout) ----
    {
        const int px = tid & 127;
        const int dh = tid >> 7;        // d half: 0 -> d 0..63, 1 -> d 64..127
        for (int g = dh * 8; g < dh * 8 + 8; ++g) {
            unsigned short s0[8], s1[8], s2[8];
#pragma unroll
            for (int j = 0; j < 8; ++j) {
                float v = xf[(g * 8 + j) * MTILE + px];
                split3(v, s0[j], s1[j], s2[j]);
            }
            const int ch = g >> 1, h = g & 1;
            const uint32_t off = (uint32_t)(ch * 4096) + swz16((uint32_t)px, (uint32_t)h);
            *(uint4*)(smem + OFF_A + 0 * A_SPLIT + off) = pack8(s0);
            *(uint4*)(smem + OFF_A + 1 * A_SPLIT + off) = pack8(s1);
            *(uint4*)(smem + OFF_A + 2 * A_SPLIT + off) = pack8(s2);
        }
    }
    __syncthreads();   // A splits ready; xf area now reusable as w buffers

    // ---- prefetch w stage 0 ----
    for (int t = tid; t < W_STAGE / 16; t += NTHREADS)
        cp16(su + OFF_W + (uint32_t)(t * 16), g_wsplit + (size_t)t * 16);
    CP_COMMIT();

    // ---- per-thread fragment addressing ----
    const int lane = tid & 31;
    const int warp = tid >> 5;          // 8 warps x 16 px
    const int px0 = warp * 16;

    // A: lanes 0-7 rows 0-7 h0 | 8-15 rows 8-15 h0 | 16-23 rows 0-7 h1 | 24-31 rows 8-15 h1
    const uint32_t ap = (uint32_t)(px0 + (lane & 7) + ((lane >> 3) & 1) * 8);
    const uint32_t ah = (uint32_t)(lane >> 4);
    const uint32_t aoff = swz16(ap, ah);
    // B: lanes 0-7 codes 0-7 h0 | 8-15 codes 0-7 h1 | 16-23 codes 8-15 h0 | 24-31 codes 8-15 h1
    const uint32_t bc = (uint32_t)((lane & 7) + ((lane >> 4) & 1) * 8);
    const uint32_t bh = (uint32_t)((lane >> 3) & 1);
    uint32_t boff[4];
#pragma unroll
    for (int ct = 0; ct < 4; ++ct) boff[ct] = swz16((uint32_t)(ct * 16) + bc, bh);

    const float x2a = x2s[px0 + (lane >> 2)];
    const float x2b = x2s[px0 + 8 + (lane >> 2)];

    float acc[8][4];
#pragma unroll
    for (int t = 0; t < 8; ++t)
#pragma unroll
        for (int q = 0; q < 4; ++q) acc[t][q] = 0.0f;

    float bdA = __int_as_float(0x7F800000), bdB = bdA;
    int bkA = 0, bkB = 0;

    for (int nt = 0; nt < NSTAGES; ++nt) {
        // prefetch next stage
        if (nt + 1 < NSTAGES) {
            const unsigned char* src = g_wsplit + (size_t)(nt + 1) * W_STAGE;
            const uint32_t dst = su + OFF_W + ((nt + 1) & 1) * W_STAGE;
            for (int t = tid; t < W_STAGE / 16; t += NTHREADS)
                cp16(dst + (uint32_t)(t * 16), src + (size_t)t * 16);
            CP_COMMIT();
            CP_WAIT(1);
        } else {
            CP_WAIT(0);
        }
        __syncthreads();

        const uint32_t wb = su + OFF_W + (nt & 1) * W_STAGE;

#pragma unroll 1
        for (int ch = 0; ch < 8; ++ch) {
            uint32_t A[3][4];
#pragma unroll
            for (int s = 0; s < 3; ++s)
                LDSM_X4(A[s][0], A[s][1], A[s][2], A[s][3],
                        su + OFF_A + s * A_SPLIT + ch * 4096 + aoff);
#pragma unroll
            for (int sb = 0; sb < 3; ++sb) {
#pragma unroll
                for (int ct = 0; ct < 4; ++ct) {
                    uint32_t b0, b1, b2, b3;
                    LDSM_X4(b0, b1, b2, b3,
                            wb + sb * W_SPLIT + ch * 2048 + boff[ct]);
#pragma unroll
                    for (int sa = 0; sa < 3; ++sa) {
                        if (sa + sb <= 2) {
                            MMA16816(acc[ct * 2 + 0], A[sa], b0, b1);
                            MMA16816(acc[ct * 2 + 1], A[sa], b2, b3);
                        }
                    }
                }
            }
        }

        // ---- stage epilogue: d2 + running argmin (ascending k within lane) ----
        const int kq = nt * NSTAGE + (lane & 3) * 2;
#pragma unroll
        for (int t = 0; t < 8; ++t) {
            const int k0 = kq + t * 8;
#pragma unroll
            for (int q = 0; q < 2; ++q) {
                const int kk = k0 + q;
                const float e2v = e2s[kk];
                float tA = __fadd_rn(x2a, __fmul_rn(-2.0f, acc[t][q]));
                float dA = __fadd_rn(tA, e2v);
                if (dA < bdA) { bdA = dA; bkA = kk; }
                float tB = __fadd_rn(x2b, __fmul_rn(-2.0f, acc[t][q + 2]));
                float dB = __fadd_rn(tB, e2v);
                if (dB < bdB) { bdB = dB; bkB = kk; }
                acc[t][q] = 0.0f;
                acc[t][q + 2] = 0.0f;
            }
        }
        __syncthreads();   // done reading wbuf(nt&1) before it is refilled
    }

    // ---- merge across lanes sharing a pixel row ----
    {
        unsigned long long pA =
            ((unsigned long long)__float_as_uint(bdA) << 32) | (unsigned)bkA;
        unsigned long long pB =
            ((unsigned long long)__float_as_uint(bdB) << 32) | (unsigned)bkB;
        atomicMin(&best[px0 + (lane >> 2)], pA);
        atomicMin(&best[px0 + 8 + (lane >> 2)], pB);
    }
    __syncthreads();

    // ---- outputs: gather codebook rows + argmin ----
    const size_t obase = ((size_t)b * DCH) * HW + hw0;
    for (int t = tid; t < DCH * MTILE; t += NTHREADS) {
        int d = t >> 7;
        int px = t & 127;
        unsigned k = (unsigned)(best[px] & 0xFFFFFFFFu);
        out[obase + (size_t)d * HW + px] = w[(size_t)d * KCODES + k];
    }
    if (write_amin && tid < MTILE) {
        unsigned k = (unsigned)(best[tid] & 0xFFFFFFFFu);
        out[RES_ELEMS + (size_t)b * HW + hw0 + tid] = (float)k;
    }
}

extern "C" void kernel_launch(void* const* d_in, const int* in_sizes, int n_in,
                              void* d_out, int out_size) {
    const float* x = (const float*)d_in[0];
    const float* w = (const float*)d_in[1];
    float* out = (float*)d_out;
    const int write_amin = ((size_t)out_size > RES_ELEMS) ? 1 : 0;

    cudaFuncSetAttribute(nearest_embed_hmma_kernel,
                         cudaFuncAttributeMaxDynamicSharedMemorySize, SMEM_TOTAL);

    convert_w_kernel<<<NSTAGES, NSTAGE>>>(w);
    nearest_embed_hmma_kernel<<<(BATCH * HW) / MTILE, NTHREADS, SMEM_TOTAL>>>(
        x, w, out, write_amin);
}

// round 8
// speedup vs baseline: 2.2424x; 1.5455x over previous
#include <cuda_runtime.h>
#include <cuda_fp16.h>
#include <cstdint>

// NearestEmbed via mma.sync (HMMA) fp16 2-split GEMM + fused argmin.
//   xe = x.w via 3 fp16 mma combos (x0w0, x0w1, x1w0), fp32 accum.
//   w scaled by 1024 (exact) before split so residuals stay normal fp16;
//   epilogue multiplies by -2/1024 (exact power of 2).
//   x2/e2: sequential fadd(rn(v*v)) ascending d (matches reference path)
//   d2 = fadd(fadd(x2, fmul(-2/1024, acc)), e2); first-index tie-break.

#define DCH 128
#define KCODES 1024
#define HW 4096
#define BATCH 32
#define RES_ELEMS ((size_t)BATCH * DCH * HW)

#define NTHREADS 512
#define MTILE 128            // pixels per CTA
#define NSTAGE 64            // codes per stage
#define NSTAGES 16

#define A_SPLIT 32768        // one fp16 split of x tile: 8 chunks x 128px x 32B
#define W_SPLIT 16384        // one fp16 split of w stage: 8 chunks x 64c x 32B
#define W_STAGE (2 * W_SPLIT)   // 32768

#define OFF_A    0           // 2 x A_SPLIT = 65536
#define OFF_W    65536       // ring: 3 x W_STAGE = 98304
#define OFF_XF   65536       // overlay: x f32 tile (65536) inside ring, pre-loop
#define OFF_E2   163840      // 1024 f32
#define OFF_X2   167936      // 128 f32
#define OFF_BEST 168448      // 128 u64
#define SMEM_TOTAL 169472

__device__ __align__(16) unsigned char g_wsplit[NSTAGES * W_STAGE];
__device__ float g_e2[KCODES];

// ---------------- helpers ----------------
__device__ __forceinline__ uint32_t smem_u32(const void* p) {
    uint32_t a;
    asm("{ .reg .u64 t; cvta.to.shared.u64 t, %1; cvt.u32.u64 %0, t; }" : "=r"(a) : "l"(p));
    return a;
}
__device__ __forceinline__ void cp16(uint32_t dst, const void* src) {
    asm volatile("cp.async.cg.shared.global [%0], [%1], 16;" :: "r"(dst), "l"(src) : "memory");
}
#define CP_COMMIT() asm volatile("cp.async.commit_group;" ::: "memory")
#define CP_WAIT(N)  asm volatile("cp.async.wait_group %0;" :: "n"(N) : "memory")

#define LDSM_X4(R0, R1, R2, R3, ADDR) \
    asm volatile("ldmatrix.sync.aligned.m8n8.x4.shared.b16 {%0,%1,%2,%3}, [%4];" \
        : "=r"(R0), "=r"(R1), "=r"(R2), "=r"(R3) : "r"(ADDR))

#define MMA16816(D, A, B0, B1) \
    asm volatile("mma.sync.aligned.m16n8k16.row.col.f32.f16.f16.f32 " \
        "{%0,%1,%2,%3}, {%4,%5,%6,%7}, {%8,%9}, {%0,%1,%2,%3};" \
        : "+f"((D)[0]), "+f"((D)[1]), "+f"((D)[2]), "+f"((D)[3]) \
        : "r"((A)[0]), "r"((A)[1]), "r"((A)[2]), "r"((A)[3]), "r"(B0), "r"(B1))

// XOR-swizzled granule offset: row p (4 px/codes per 128B row), k-half h.
__device__ __host__ __forceinline__ uint32_t swz16(uint32_t p, uint32_t h) {
    uint32_t r = p >> 2;
    uint32_t col = (((p & 3u) * 2u + h) ^ (r & 7u));
    return r * 128u + col * 16u;
}

// exact fp32 -> fp16 hi/lo split (residual subtraction is exact: <=13 sig bits)
__device__ __forceinline__ void split2(float v, unsigned short& s0, unsigned short& s1) {
    __half h0 = __float2half_rn(v);
    float r = v - __half2float(h0);
    __half h1 = __float2half_rn(r);
    s0 = __half_as_ushort(h0);
    s1 = __half_as_ushort(h1);
}
__device__ __forceinline__ uint4 pack8(const unsigned short* s) {
    uint4 v;
    v.x = (uint32_t)s[0] | ((uint32_t)s[1] << 16);
    v.y = (uint32_t)s[2] | ((uint32_t)s[3] << 16);
    v.z = (uint32_t)s[4] | ((uint32_t)s[5] << 16);
    v.w = (uint32_t)s[6] | ((uint32_t)s[7] << 16);
    return v;
}

// ---------------- prep: e2 (exact) + scaled fp16 2-splits of w ----------------
__global__ void convert_w_kernel(const float* __restrict__ w) {
    const int nt = blockIdx.x;        // stage (64 codes)
    const int c = threadIdx.x;        // local code 0..63
    const int k = nt * NSTAGE + c;
    float e2 = 0.0f;
    for (int g = 0; g < 16; ++g) {    // granule g: d = 8g..8g+7 ascending
        unsigned short s0[8], s1[8];
#pragma unroll
        for (int j = 0; j < 8; ++j) {
            float v = w[(size_t)(g * 8 + j) * KCODES + k];
            e2 = __fadd_rn(e2, __fmul_rn(v, v));
            split2(v * 1024.0f, s0[j], s1[j]);   // exact scale by 2^10
        }
        const int ch = g >> 1, h = g & 1;
        unsigned char* base = g_wsplit + (size_t)nt * W_STAGE + (size_t)ch * 2048
                            + swz16((uint32_t)c, (uint32_t)h);
        *(uint4*)(base + 0 * W_SPLIT) = pack8(s0);
        *(uint4*)(base + 1 * W_SPLIT) = pack8(s1);
    }
    g_e2[k] = e2;
}

// ---------------- main ----------------
__global__ __launch_bounds__(NTHREADS, 1)
void nearest_embed_hmma_kernel(const float* __restrict__ x,
                               const float* __restrict__ w,
                               float* __restrict__ out,
                               int write_amin) {
    extern __shared__ char smem[];
    const uint32_t su = smem_u32(smem);
    const int tid = threadIdx.x;
    const int blk = blockIdx.x;
    const int b = blk >> 5;
    const int hw0 = (blk & 31) * MTILE;

    float* e2s = (float*)(smem + OFF_E2);
    float* x2s = (float*)(smem + OFF_X2);
    unsigned long long* best = (unsigned long long*)(smem + OFF_BEST);

    if (tid < MTILE) best[tid] = 0xFFFFFFFFFFFFFFFFull;
    for (int i = tid; i < KCODES; i += NTHREADS) e2s[i] = g_e2[i];

    // ---- stage x f32 tile [128d][128px] into OFF_XF ----
    const float* xbase = x + ((size_t)b * DCH) * HW + hw0;
    for (int t = tid; t < DCH * 32; t += NTHREADS) {
        int d = t >> 5, q = t & 31;
        cp16(su + OFF_XF + (uint32_t)(d * 512 + q * 16),
             xbase + (size_t)d * HW + q * 4);
    }
    CP_COMMIT();
    CP_WAIT(0);
    __syncthreads();

    // ---- x2 (exact sequential ascending d) ----
    const float* xf = (const float*)(smem + OFF_XF);
    if (tid < MTILE) {
        float a = 0.0f;
        for (int d = 0; d < DCH; ++d) {
            float v = xf[d * MTILE + tid];
            a = __fadd_rn(a, __fmul_rn(v, v));
        }
        x2s[tid] = a;
    }

    // ---- convert x tile -> 2 fp16 splits (swizzled A layout) ----
    {
        const int px = tid & 127;
        const int quarter = tid >> 7;        // 0..3 -> 4 granules each
        for (int g = quarter * 4; g < quarter * 4 + 4; ++g) {
            unsigned short s0[8], s1[8];
#pragma unroll
            for (int j = 0; j < 8; ++j)
                split2(xf[(g * 8 + j) * MTILE + px], s0[j], s1[j]);
            const int ch = g >> 1, h = g & 1;
            const uint32_t off = (uint32_t)(ch * 4096) + swz16((uint32_t)px, (uint32_t)h);
            *(uint4*)(smem + OFF_A + 0 * A_SPLIT + off) = pack8(s0);
            *(uint4*)(smem + OFF_A + 1 * A_SPLIT + off) = pack8(s1);
        }
    }
    __syncthreads();   // A ready; XF area (ring slots 0-1) now reusable

    // ---- prefetch w stages 0 and 1 ----
    for (int s = 0; s < 2; ++s) {
        const unsigned char* src = g_wsplit + (size_t)s * W_STAGE;
        const uint32_t dst = su + OFF_W + s * W_STAGE;
        for (int t = tid; t < W_STAGE / 16; t += NTHREADS)
            cp16(dst + (uint32_t)(t * 16), src + (size_t)t * 16);
        CP_COMMIT();
    }

    // ---- per-thread fragment addressing ----
    const int lane = tid & 31;
    const int warp = tid >> 5;          // 16 warps: 8 px-groups x 2 code-halves
    const int pg = warp >> 1;
    const int chalf = warp & 1;
    const int px0 = pg * 16;

    const uint32_t ap = (uint32_t)(px0 + (lane & 7) + ((lane >> 3) & 1) * 8);
    const uint32_t ah = (uint32_t)(lane >> 4);
    const uint32_t aoff = swz16(ap, ah);
    const uint32_t bc = (uint32_t)((lane & 7) + ((lane >> 4) & 1) * 8);
    const uint32_t bh = (uint32_t)((lane >> 3) & 1);
    uint32_t boff[2];
#pragma unroll
    for (int ct = 0; ct < 2; ++ct)
        boff[ct] = swz16((uint32_t)(chalf * 32 + ct * 16) + bc, bh);

    const float x2a = x2s[px0 + (lane >> 2)];
    const float x2b = x2s[px0 + 8 + (lane >> 2)];

    float acc[4][4];
#pragma unroll
    for (int t = 0; t < 4; ++t)
#pragma unroll
        for (int q = 0; q < 4; ++q) acc[t][q] = 0.0f;

    float bdA = __int_as_float(0x7F800000), bdB = bdA;
    int bkA = 0, bkB = 0;

    for (int nt = 0; nt < NSTAGES; ++nt) {
        __syncthreads();   // prev stage fully consumed -> ring slot (nt+2)%3 free

        if (nt + 2 < NSTAGES) {
            const unsigned char* src = g_wsplit + (size_t)(nt + 2) * W_STAGE;
            const uint32_t dst = su + OFF_W + ((nt + 2) % 3) * W_STAGE;
            for (int t = tid; t < W_STAGE / 16; t += NTHREADS)
                cp16(dst + (uint32_t)(t * 16), src + (size_t)t * 16);
            CP_COMMIT();
            CP_WAIT(2);
        } else if (nt == NSTAGES - 2) {
            CP_WAIT(1);
        } else {
            CP_WAIT(0);
        }
        __syncthreads();   // stage nt visible to all threads

        const uint32_t wb = su + OFF_W + (nt % 3) * W_STAGE;

#pragma unroll 1
        for (int ch = 0; ch < 8; ++ch) {
            uint32_t A0[4], A1[4];
            LDSM_X4(A0[0], A0[1], A0[2], A0[3],
                    su + OFF_A + 0 * A_SPLIT + ch * 4096 + aoff);
            LDSM_X4(A1[0], A1[1], A1[2], A1[3],
                    su + OFF_A + 1 * A_SPLIT + ch * 4096 + aoff);
#pragma unroll
            for (int ct = 0; ct < 2; ++ct) {
                uint32_t b0, b1, b2, b3;
                // w0 fragment: combos x0*w0, x1*w0
                LDSM_X4(b0, b1, b2, b3, wb + 0 * W_SPLIT + ch * 2048 + boff[ct]);
                MMA16816(acc[ct * 2 + 0], A0, b0, b1);
                MMA16816(acc[ct * 2 + 1], A0, b2, b3);
                MMA16816(acc[ct * 2 + 0], A1, b0, b1);
                MMA16816(acc[ct * 2 + 1], A1, b2, b3);
                // w1 fragment: combo x0*w1
                LDSM_X4(b0, b1, b2, b3, wb + 1 * W_SPLIT + ch * 2048 + boff[ct]);
                MMA16816(acc[ct * 2 + 0], A0, b0, b1);
                MMA16816(acc[ct * 2 + 1], A0, b2, b3);
            }
        }

        // ---- stage epilogue: d2 + running argmin (ascending k) ----
        const int kq = nt * NSTAGE + chalf * 32 + (lane & 3) * 2;
#pragma unroll
        for (int t = 0; t < 4; ++t) {
            const int k0 = kq + t * 8;
#pragma unroll
            for (int q = 0; q < 2; ++q) {
                const int kk = k0 + q;
                const float e2v = e2s[kk];
                // acc holds xe*1024; -2*xe == (-2/1024)*acc, both scalings exact
                float tA = __fadd_rn(x2a, __fmul_rn(-0.001953125f, acc[t][q]));
                float dA = __fadd_rn(tA, e2v);
                if (dA < bdA) { bdA = dA; bkA = kk; }
                float tB = __fadd_rn(x2b, __fmul_rn(-0.001953125f, acc[t][q + 2]));
                float dB = __fadd_rn(tB, e2v);
                if (dB < bdB) { bdB = dB; bkB = kk; }
                acc[t][q] = 0.0f;
                acc[t][q + 2] = 0.0f;
            }
        }
    }

    // ---- merge across lanes/warps sharing a pixel ----
    {
        unsigned long long pA =
            ((unsigned long long)__float_as_uint(bdA) << 32) | (unsigned)bkA;
        unsigned long long pB =
            ((unsigned long long)__float_as_uint(bdB) << 32) | (unsigned)bkB;
        atomicMin(&best[px0 + (lane >> 2)], pA);
        atomicMin(&best[px0 + 8 + (lane >> 2)], pB);
    }
    __syncthreads();

    // ---- outputs: gather codebook rows + argmin ----
    const size_t obase = ((size_t)b * DCH) * HW + hw0;
    for (int t = tid; t < DCH * MTILE; t += NTHREADS) {
        int d = t >> 7;
        int px = t & 127;
        unsigned k = (unsigned)(best[px] & 0xFFFFFFFFu);
        out[obase + (size_t)d * HW + px] = w[(size_t)d * KCODES + k];
    }
    if (write_amin && tid < MTILE) {
        unsigned k = (unsigned)(best[tid] & 0xFFFFFFFFu);
        out[RES_ELEMS + (size_t)b * HW + hw0 + tid] = (float)k;
    }
}

extern "C" void kernel_launch(void* const* d_in, const int* in_sizes, int n_in,
                              void* d_out, int out_size) {
    const float* x = (const float*)d_in[0];
    const float* w = (const float*)d_in[1];
    float* out = (float*)d_out;
    const int write_amin = ((size_t)out_size > RES_ELEMS) ? 1 : 0;

    cudaFuncSetAttribute(nearest_embed_hmma_kernel,
                         cudaFuncAttributeMaxDynamicSharedMemorySize, SMEM_TOTAL);

    convert_w_kernel<<<NSTAGES, NSTAGE>>>(w);
    nearest_embed_hmma_kernel<<<(BATCH * HW) / MTILE, NTHREADS, SMEM_TOTAL>>>(
        x, w, out, write_amin);
}